// round 9
// baseline (speedup 1.0000x reference)
#include <cuda_runtime.h>
#include <cuda_fp16.h>
#include <math.h>
#include <stdint.h>

#define BSZ 8
#define CCH 512
#define TT  8192
#define NEL (BSZ*CCH*TT)
#define KW  3

// ---- conv tiling: CTA = 64 co x 256 t, 4 warps (warp tile 64x64), 3-stage ----
#define MCO 64
#define NTT 256
#define CC  32                        // ci per pipeline stage
#define NCHUNK (CCH/CC)               // 16
#define ROWB 80                       // 32 fp16 = 64B data + 16B pad
#define A_TILE (64*ROWB)              // 5120  (one tap tile: 64 co rows)
#define BROWS 264                     // 256 t + 2 halo, padded to mult of 8
#define B_TILE (BROWS*ROWB)           // 21120
#define SM_BOFF (3*A_TILE)            // 15360
#define STAGE (3*A_TILE + B_TILE)     // 36480
#define NSTAGE 3
#define SM_TOTAL (NSTAGE*STAGE)       // 109440 per CTA (2 CTAs/SM)
#define CTN 128                       // 4 warps

// ---------------- scratch ------------------------------------------------------
__device__ __half g_actT[NEL];            // [b][t][ci] fp16
__device__ float  g_c1[NEL];              // conv1 out [b][co][t]
__device__ __half g_w1[3*CCH*CCH];        // [tap][co][ci] fp16
__device__ __half g_w2[3*CCH*CCH];
__device__ float  g_a2c[2*CCH];
__device__ float  g_binv[2*CCH];

// ---------------- PTX helpers ---------------------------------------------------
__device__ __forceinline__ void cp16(uint32_t dst, const void* src, bool pred) {
    asm volatile("cp.async.ca.shared.global [%0], [%1], 16, %2;"
                 :: "r"(dst), "l"(src), "r"(pred ? 16 : 0));
}
__device__ __forceinline__ void cp_commit() { asm volatile("cp.async.commit_group;"); }
template<int N> __device__ __forceinline__ void cp_wait() {
    asm volatile("cp.async.wait_group %0;" :: "n"(N));
}
__device__ __forceinline__ void ldx4(uint32_t* r, uint32_t addr) {
    asm volatile("ldmatrix.sync.aligned.m8n8.x4.shared.b16 {%0,%1,%2,%3}, [%4];"
                 : "=r"(r[0]), "=r"(r[1]), "=r"(r[2]), "=r"(r[3]) : "r"(addr));
}
__device__ __forceinline__ void mma16816(float* d, const uint32_t* a, const uint32_t* b) {
    asm volatile(
        "mma.sync.aligned.m16n8k16.row.col.f32.f16.f16.f32 "
        "{%0,%1,%2,%3}, {%4,%5,%6,%7}, {%8,%9}, {%0,%1,%2,%3};"
        : "+f"(d[0]), "+f"(d[1]), "+f"(d[2]), "+f"(d[3])
        : "r"(a[0]), "r"(a[1]), "r"(a[2]), "r"(a[3]), "r"(b[0]), "r"(b[1]));
}

// ---------------- kernel 1: weight norm -> fp16 [tap][co][ci] -------------------
__global__ void wnorm_kernel(const float* __restrict__ v, const float* __restrict__ g,
                             const float* __restrict__ alpha, const float* __restrict__ beta,
                             __half* __restrict__ wsp,
                             float* __restrict__ a2out, float* __restrict__ binvout)
{
    int co = blockIdx.x;
    const float* vc = v + co * (CCH * KW);
    float s = 0.f;
    for (int i = threadIdx.x; i < CCH * KW; i += 256) { float t = vc[i]; s += t * t; }
    __shared__ float red[256];
    red[threadIdx.x] = s;
    __syncthreads();
    for (int off = 128; off > 0; off >>= 1) {
        if (threadIdx.x < off) red[threadIdx.x] += red[threadIdx.x + off];
        __syncthreads();
    }
    float scale = g[co] / sqrtf(red[0]);
    for (int i = threadIdx.x; i < CCH * KW; i += 256) {
        int ci = i / KW, k = i % KW;
        wsp[((size_t)k * CCH + co) * CCH + ci] = __float2half(vc[i] * scale);
    }
    if (threadIdx.x == 0) {
        a2out[co]   = 2.f * expf(alpha[co]);
        binvout[co] = 1.f / (2.f * expf(beta[co]) + 1e-9f);
    }
}

// ---------------- kernel 2: SnakeBeta Activation1d + transpose -> fp16 ----------
#define ATI 64
#define ATT 64
__global__ __launch_bounds__(256)
void snake_actT_kernel(const float* __restrict__ in,
                       const float* __restrict__ a2,
                       const float* __restrict__ binv,
                       __half* __restrict__ oA)
{
    __shared__ float xs[ATI][ATT + 3];
    int tid = threadIdx.x;
    int b = blockIdx.z, ci0 = blockIdx.y * ATI, t0 = blockIdx.x * ATT;
    const float* xb = in + ((size_t)b * CCH + ci0) * TT;

    for (int e = tid; e < ATI * (ATT + 2); e += 256) {
        int r = e / (ATT + 2);
        int c = e - r * (ATT + 2);
        int t = t0 - 1 + c;
        float v;
        if (t < 0)        v = 0.f;
        else if (t >= TT) v = xb[r * TT + (TT - 1)];
        else              v = xb[r * TT + t];
        xs[r][c] = v;
    }
    __syncthreads();

    int w = tid >> 5, l = tid & 31;
    int ci = (w & 1) * 32 + l;
    int wt = w >> 1;
    float aa = a2[ci0 + ci];
    float bi = 0.5f * binv[ci0 + ci];
#pragma unroll 4
    for (int s = 0; s < 16; s++) {
        int tl = wt * 16 + s;
        int t  = t0 + tl;
        float xm = xs[ci][tl], x0 = xs[ci][tl + 1], xp = xs[ci][tl + 2];
        float u0 = (t > 0) ? fmaf(0.25f, xm, 0.75f * x0) : x0;
        float u1 = fmaf(0.25f, xp, 0.75f * x0);
        float y  = 0.5f * (u0 + u1)
                 + (1.f - __cosf(aa * u0)) * bi
                 + (1.f - __cosf(aa * u1)) * bi;
        oA[((size_t)b * TT + t) * CCH + ci0 + ci] = __float2half(y);
    }
}

// ---------------- kernel 3: conv via mma.sync fp16 ------------------------------
// CTA 64co x 256t, 4 warps (warp tile 64x64 along t), 3-stage cp.async ring,
// one __syncthreads per chunk, issue-before-compute. 2 CTA/SM.
__global__ __launch_bounds__(CTN, 2)
void conv_mma_kernel(const __half* __restrict__ aA,
                     const __half* __restrict__ Wsp,
                     const float* __restrict__ bias,
                     const float* __restrict__ resid,
                     float* __restrict__ out)
{
    extern __shared__ char smem[];
    const uint32_t sbase = (uint32_t)__cvta_generic_to_shared(smem);
    const int tid  = threadIdx.x;
    const int wid  = tid >> 5, lane = tid & 31;
    const int gid  = lane >> 2, tig = lane & 3;
    const int b    = blockIdx.z;
    const int co0  = blockIdx.y * MCO;
    const int t0   = blockIdx.x * NTT;

    float acc[4][8][4];
#pragma unroll
    for (int m = 0; m < 4; m++)
#pragma unroll
        for (int n = 0; n < 8; n++)
#pragma unroll
            for (int q = 0; q < 4; q++) acc[m][n][q] = 0.f;

    const __half* aBase = aA + (size_t)b * TT * CCH;

    // ---- stage issue: chunk ch -> buffer ch % 3 ----
    // A: 3 tap tiles [64co][32ci] = 3*64*4 = 768 segs; B: [264t][32ci] = 1056 segs
    auto issue = [&](int ch) {
        const int ci0 = ch * CC;
        const uint32_t sb = sbase + (uint32_t)(ch % NSTAGE) * STAGE;
        for (int u = tid; u < 768 + 1056; u += CTN) {
            if (u < 768) {
                int tile = u >> 8;              // tap
                int rem  = u & 255;
                int row  = rem >> 2;            // co
                int seg  = rem & 3;
                const __half* src =
                    Wsp + ((size_t)(tile * CCH + co0 + row)) * CCH + ci0 + seg * 8;
                cp16(sb + tile * A_TILE + row * ROWB + seg * 16, src, true);
            } else {
                int u2  = u - 768;
                int row = u2 >> 2;              // t halo row
                int seg = u2 & 3;
                int t   = t0 - 1 + row;
                bool ok = (t >= 0 && t < TT && row < 258);
                int tc  = ok ? t : 0;
                const __half* src = aBase + (size_t)tc * CCH + ci0 + seg * 8;
                cp16(sb + SM_BOFF + row * ROWB + seg * 16, src, ok);
            }
        }
        cp_commit();
    };

    issue(0);
    issue(1);

    const uint32_t aoffb = (uint32_t)((lane & 15) * ROWB + (lane >> 4) * 16);
    const uint32_t boffb = (uint32_t)(((lane & 7) + ((lane >> 4) << 3) + wid * 64) * ROWB
                                      + ((lane >> 3) & 1) * 16);

    for (int ch = 0; ch < NCHUNK; ch++) {
        cp_wait<1>();
        __syncthreads();
        if (ch + 2 < NCHUNK) issue(ch + 2);

        const uint32_t sb = sbase + (uint32_t)(ch % NSTAGE) * STAGE;
        const uint32_t abase = sb + aoffb;
        const uint32_t bbase = sb + SM_BOFF + boffb;
#pragma unroll
        for (int ks = 0; ks < 2; ks++) {
#pragma unroll
            for (int tap = 0; tap < 3; tap++) {
                uint32_t bq[4][4];
#pragma unroll
                for (int np = 0; np < 4; np++)
                    ldx4(bq[np], bbase + (uint32_t)((np * 16 + tap) * ROWB + ks * 32));
#pragma unroll
                for (int m = 0; m < 4; m++) {
                    uint32_t af[4];
                    ldx4(af, abase + (uint32_t)(tap * A_TILE + m * 16 * ROWB + ks * 32));
#pragma unroll
                    for (int np = 0; np < 4; np++) {
                        mma16816(acc[m][2 * np],     af, &bq[np][0]);
                        mma16816(acc[m][2 * np + 1], af, &bq[np][2]);
                    }
                }
            }
        }
    }

    // ---- epilogue ----
#pragma unroll
    for (int m = 0; m < 4; m++) {
        int r0 = co0 + m * 16 + gid;
        int r1 = r0 + 8;
        float b0 = bias[r0], b1 = bias[r1];
        size_t o0 = ((size_t)(b * CCH + r0)) * TT + t0;
        size_t o1 = ((size_t)(b * CCH + r1)) * TT + t0;
#pragma unroll
        for (int n = 0; n < 8; n++) {
            int tof = wid * 64 + n * 8 + 2 * tig;
            float2 v0 = make_float2(acc[m][n][0] + b0, acc[m][n][1] + b0);
            float2 v1 = make_float2(acc[m][n][2] + b1, acc[m][n][3] + b1);
            if (resid) {
                float2 rv0 = *(const float2*)(resid + o0 + tof);
                float2 rv1 = *(const float2*)(resid + o1 + tof);
                v0.x += rv0.x; v0.y += rv0.y;
                v1.x += rv1.x; v1.y += rv1.y;
            }
            *(float2*)(out + o0 + tof) = v0;
            *(float2*)(out + o1 + tof) = v1;
        }
    }
}

// ---------------------------------- launch ---------------------------------------
extern "C" void kernel_launch(void* const* d_in, const int* in_sizes, int n_in,
                              void* d_out, int out_size)
{
    const float* x      = (const float*)d_in[0];
    const float* v1     = (const float*)d_in[1];
    const float* g1     = (const float*)d_in[2];
    const float* bias1  = (const float*)d_in[3];
    const float* v2     = (const float*)d_in[4];
    const float* g2     = (const float*)d_in[5];
    const float* bias2  = (const float*)d_in[6];
    const float* alpha1 = (const float*)d_in[7];
    const float* beta1  = (const float*)d_in[8];
    const float* alpha2 = (const float*)d_in[9];
    const float* beta2  = (const float*)d_in[10];
    float* out = (float*)d_out;

    __half *aA, *w1, *w2;
    float *c1, *a2c, *binv;
    cudaGetSymbolAddress((void**)&aA,   g_actT);
    cudaGetSymbolAddress((void**)&c1,   g_c1);
    cudaGetSymbolAddress((void**)&w1,   g_w1);
    cudaGetSymbolAddress((void**)&w2,   g_w2);
    cudaGetSymbolAddress((void**)&a2c,  g_a2c);
    cudaGetSymbolAddress((void**)&binv, g_binv);

    static bool attr_set = false;
    if (!attr_set) {
        cudaFuncSetAttribute(conv_mma_kernel,
                             cudaFuncAttributeMaxDynamicSharedMemorySize, SM_TOTAL);
        attr_set = true;
    }

    wnorm_kernel<<<CCH, 256>>>(v1, g1, alpha1, beta1, w1, a2c,       binv);
    wnorm_kernel<<<CCH, 256>>>(v2, g2, alpha2, beta2, w2, a2c + CCH, binv + CCH);

    dim3 agrid(TT / ATT, CCH / ATI, BSZ);
    dim3 cgrid(TT / NTT, CCH / MCO, BSZ);

    snake_actT_kernel<<<agrid, 256>>>(x, a2c, binv, aA);
    conv_mma_kernel<<<cgrid, CTN, SM_TOTAL>>>(aA, w1, bias1, nullptr, c1);
    snake_actT_kernel<<<agrid, 256>>>(c1, a2c + CCH, binv + CCH, aA);
    conv_mma_kernel<<<cgrid, CTN, SM_TOTAL>>>(aA, w2, bias2, x, out);
}

// round 10
// speedup vs baseline: 1.0475x; 1.0475x over previous
#include <cuda_runtime.h>
#include <cuda_fp16.h>
#include <math.h>
#include <stdint.h>

#define BSZ 8
#define CCH 512
#define TT  8192
#define NEL (BSZ*CCH*TT)
#define KW  3

// ---- conv tiling: tile = 64 co x 256 t, 4 warps, 3-stage ring, persistent ----
#define MCO 64
#define NTT 256
#define CC  32
#define NCHUNK (CCH/CC)               // 16 chunks per tile
#define ROWB 80
#define A_TILE (64*ROWB)              // 5120
#define BROWS 264
#define B_TILE (BROWS*ROWB)           // 21120
#define SM_BOFF (3*A_TILE)            // 15360
#define STAGE (3*A_TILE + B_TILE)     // 36480
#define NSTAGE 3
#define SM_TOTAL (NSTAGE*STAGE)       // 109440 (2 CTA/SM)
#define CTN 128
#define GRID 296                      // persistent CTAs (2 x 148 SMs)
#define NTILE (BSZ*(CCH/MCO)*(TT/NTT))// 8*8*32 = 2048

// ---------------- scratch ------------------------------------------------------
__device__ __half g_actT[NEL];            // [b][t][ci] fp16
__device__ float  g_c1[NEL];              // conv1 out [b][co][t]
__device__ __half g_w1[3*CCH*CCH];        // [tap][co][ci] fp16
__device__ __half g_w2[3*CCH*CCH];
__device__ float  g_a2c[2*CCH];
__device__ float  g_binv[2*CCH];

// ---------------- PTX helpers ---------------------------------------------------
__device__ __forceinline__ void cp16(uint32_t dst, const void* src, bool pred) {
    asm volatile("cp.async.ca.shared.global [%0], [%1], 16, %2;"
                 :: "r"(dst), "l"(src), "r"(pred ? 16 : 0));
}
__device__ __forceinline__ void cp_commit() { asm volatile("cp.async.commit_group;"); }
template<int N> __device__ __forceinline__ void cp_wait() {
    asm volatile("cp.async.wait_group %0;" :: "n"(N));
}
__device__ __forceinline__ void ldx4(uint32_t* r, uint32_t addr) {
    asm volatile("ldmatrix.sync.aligned.m8n8.x4.shared.b16 {%0,%1,%2,%3}, [%4];"
                 : "=r"(r[0]), "=r"(r[1]), "=r"(r[2]), "=r"(r[3]) : "r"(addr));
}
__device__ __forceinline__ void mma16816(float* d, const uint32_t* a, const uint32_t* b) {
    asm volatile(
        "mma.sync.aligned.m16n8k16.row.col.f32.f16.f16.f32 "
        "{%0,%1,%2,%3}, {%4,%5,%6,%7}, {%8,%9}, {%0,%1,%2,%3};"
        : "+f"(d[0]), "+f"(d[1]), "+f"(d[2]), "+f"(d[3])
        : "r"(a[0]), "r"(a[1]), "r"(a[2]), "r"(a[3]), "r"(b[0]), "r"(b[1]));
}

// ---------------- kernel 1: weight norm -> fp16 [tap][co][ci] -------------------
__global__ void wnorm_kernel(const float* __restrict__ v, const float* __restrict__ g,
                             const float* __restrict__ alpha, const float* __restrict__ beta,
                             __half* __restrict__ wsp,
                             float* __restrict__ a2out, float* __restrict__ binvout)
{
    int co = blockIdx.x;
    const float* vc = v + co * (CCH * KW);
    float s = 0.f;
    for (int i = threadIdx.x; i < CCH * KW; i += 256) { float t = vc[i]; s += t * t; }
    __shared__ float red[256];
    red[threadIdx.x] = s;
    __syncthreads();
    for (int off = 128; off > 0; off >>= 1) {
        if (threadIdx.x < off) red[threadIdx.x] += red[threadIdx.x + off];
        __syncthreads();
    }
    float scale = g[co] / sqrtf(red[0]);
    for (int i = threadIdx.x; i < CCH * KW; i += 256) {
        int ci = i / KW, k = i % KW;
        wsp[((size_t)k * CCH + co) * CCH + ci] = __float2half(vc[i] * scale);
    }
    if (threadIdx.x == 0) {
        a2out[co]   = 2.f * expf(alpha[co]);
        binvout[co] = 1.f / (2.f * expf(beta[co]) + 1e-9f);
    }
}

// ---------------- kernel 2: SnakeBeta Activation1d + transpose -> fp16 ----------
// 2 ci per thread -> __half2 stores (128B per warp-store)
#define ATI 64
#define ATT 64
__global__ __launch_bounds__(256)
void snake_actT_kernel(const float* __restrict__ in,
                       const float* __restrict__ a2,
                       const float* __restrict__ binv,
                       __half* __restrict__ oA)
{
    __shared__ float xs[ATI][ATT + 3];
    int tid = threadIdx.x;
    int b = blockIdx.z, ci0 = blockIdx.y * ATI, t0 = blockIdx.x * ATT;
    const float* xb = in + ((size_t)b * CCH + ci0) * TT;

    for (int e = tid; e < ATI * (ATT + 2); e += 256) {
        int r = e / (ATT + 2);
        int c = e - r * (ATT + 2);
        int t = t0 - 1 + c;
        float v;
        if (t < 0)        v = 0.f;
        else if (t >= TT) v = xb[r * TT + (TT - 1)];
        else              v = xb[r * TT + t];
        xs[r][c] = v;
    }
    __syncthreads();

    int w = tid >> 5, l = tid & 31;
    int ciA = 2 * l, ciB = 2 * l + 1;
    float aaA = a2[ci0 + ciA], biA = 0.5f * binv[ci0 + ciA];
    float aaB = a2[ci0 + ciB], biB = 0.5f * binv[ci0 + ciB];
#pragma unroll 2
    for (int s = 0; s < 8; s++) {
        int tl = w * 8 + s;
        int t  = t0 + tl;
        float xmA = xs[ciA][tl], x0A = xs[ciA][tl + 1], xpA = xs[ciA][tl + 2];
        float xmB = xs[ciB][tl], x0B = xs[ciB][tl + 1], xpB = xs[ciB][tl + 2];
        float u0A = (t > 0) ? fmaf(0.25f, xmA, 0.75f * x0A) : x0A;
        float u0B = (t > 0) ? fmaf(0.25f, xmB, 0.75f * x0B) : x0B;
        float u1A = fmaf(0.25f, xpA, 0.75f * x0A);
        float u1B = fmaf(0.25f, xpB, 0.75f * x0B);
        float yA = 0.5f * (u0A + u1A)
                 + (1.f - __cosf(aaA * u0A)) * biA
                 + (1.f - __cosf(aaA * u1A)) * biA;
        float yB = 0.5f * (u0B + u1B)
                 + (1.f - __cosf(aaB * u0B)) * biB
                 + (1.f - __cosf(aaB * u1B)) * biB;
        *(__half2*)(oA + ((size_t)b * TT + t) * CCH + ci0 + ciA)
            = __floats2half2_rn(yA, yB);
    }
}

// ---------------- kernel 3: persistent conv via mma.sync fp16 -------------------
// 296 persistent CTAs; continuous 3-stage cp.async ring across tiles; epilogue
// overlaps next tile's staging.
__global__ __launch_bounds__(CTN, 2)
void conv_mma_kernel(const __half* __restrict__ aA,
                     const __half* __restrict__ Wsp,
                     const float* __restrict__ bias,
                     const float* __restrict__ resid,
                     float* __restrict__ out)
{
    extern __shared__ char smem[];
    const uint32_t sbase = (uint32_t)__cvta_generic_to_shared(smem);
    const int tid  = threadIdx.x;
    const int wid  = tid >> 5, lane = tid & 31;
    const int gid  = lane >> 2, tig = lane & 3;
    const int bid  = blockIdx.x;

    const int nt = (NTILE - 1 - bid) / GRID + 1;   // tiles for this CTA
    const int nG = nt * NCHUNK;                    // chunks for this CTA

    float acc[4][8][4];
#pragma unroll
    for (int m = 0; m < 4; m++)
#pragma unroll
        for (int n = 0; n < 8; n++)
#pragma unroll
            for (int q = 0; q < 4; q++) acc[m][n][q] = 0.f;

    // ---- stage issue for global chunk G (tile = bid + (G/16)*GRID, ch = G%16) --
    auto issueG = [&](int G) {
        int tau = bid + (G >> 4) * GRID;
        if (tau >= NTILE) { cp_commit(); return; }
        int ch  = G & 15;
        int ti  = tau & 31;
        int cog = (tau >> 5) & 7;
        int bb  = tau >> 8;
        int co0 = cog * MCO;
        int t0  = ti * NTT;
        int ci0 = ch * CC;
        const __half* aBase = aA + (size_t)bb * TT * CCH;
        const uint32_t sb = sbase + (uint32_t)(G % NSTAGE) * STAGE;
        for (int u = tid; u < 768 + 1056; u += CTN) {
            if (u < 768) {
                int tile = u >> 8;
                int rem  = u & 255;
                int row  = rem >> 2;
                int seg  = rem & 3;
                const __half* src =
                    Wsp + ((size_t)(tile * CCH + co0 + row)) * CCH + ci0 + seg * 8;
                cp16(sb + tile * A_TILE + row * ROWB + seg * 16, src, true);
            } else {
                int u2  = u - 768;
                int row = u2 >> 2;
                int seg = u2 & 3;
                int t   = t0 - 1 + row;
                bool ok = (t >= 0 && t < TT && row < NTT + 2);
                int tc  = ok ? t : 0;
                const __half* src = aBase + (size_t)tc * CCH + ci0 + seg * 8;
                cp16(sb + SM_BOFF + row * ROWB + seg * 16, src, ok);
            }
        }
        cp_commit();
    };

    issueG(0);
    issueG(1);

    const uint32_t aoffb = (uint32_t)((lane & 15) * ROWB + (lane >> 4) * 16);
    const uint32_t boffb = (uint32_t)(((lane & 7) + ((lane >> 4) << 3) + wid * 64) * ROWB
                                      + ((lane >> 3) & 1) * 16);

    for (int G = 0; G < nG; G++) {
        cp_wait<1>();
        __syncthreads();
        issueG(G + 2);

        const uint32_t sb = sbase + (uint32_t)(G % NSTAGE) * STAGE;
        const uint32_t abase = sb + aoffb;
        const uint32_t bbase = sb + SM_BOFF + boffb;
#pragma unroll
        for (int ks = 0; ks < 2; ks++) {
#pragma unroll
            for (int tap = 0; tap < 3; tap++) {
                uint32_t bq[4][4];
#pragma unroll
                for (int np = 0; np < 4; np++)
                    ldx4(bq[np], bbase + (uint32_t)((np * 16 + tap) * ROWB + ks * 32));
#pragma unroll
                for (int m = 0; m < 4; m++) {
                    uint32_t af[4];
                    ldx4(af, abase + (uint32_t)(tap * A_TILE + m * 16 * ROWB + ks * 32));
#pragma unroll
                    for (int np = 0; np < 4; np++) {
                        mma16816(acc[m][2 * np],     af, &bq[np][0]);
                        mma16816(acc[m][2 * np + 1], af, &bq[np][2]);
                    }
                }
            }
        }

        if ((G & 15) == 15) {
            // ---- epilogue for tile (overlaps already-issued next-tile staging) --
            int tau = bid + (G >> 4) * GRID;
            int ti  = tau & 31;
            int cog = (tau >> 5) & 7;
            int bb  = tau >> 8;
            int co0 = cog * MCO;
            int t0  = ti * NTT;
#pragma unroll
            for (int m = 0; m < 4; m++) {
                int r0 = co0 + m * 16 + gid;
                int r1 = r0 + 8;
                float b0 = bias[r0], b1 = bias[r1];
                size_t o0 = ((size_t)(bb * CCH + r0)) * TT + t0;
                size_t o1 = ((size_t)(bb * CCH + r1)) * TT + t0;
#pragma unroll
                for (int n = 0; n < 8; n++) {
                    int tof = wid * 64 + n * 8 + 2 * tig;
                    float2 v0 = make_float2(acc[m][n][0] + b0, acc[m][n][1] + b0);
                    float2 v1 = make_float2(acc[m][n][2] + b1, acc[m][n][3] + b1);
                    if (resid) {
                        float2 rv0 = *(const float2*)(resid + o0 + tof);
                        float2 rv1 = *(const float2*)(resid + o1 + tof);
                        v0.x += rv0.x; v0.y += rv0.y;
                        v1.x += rv1.x; v1.y += rv1.y;
                    }
                    *(float2*)(out + o0 + tof) = v0;
                    *(float2*)(out + o1 + tof) = v1;
#pragma unroll
                    for (int q = 0; q < 4; q++) acc[m][n][q] = 0.f;
                }
            }
        }
    }
}

// ---------------------------------- launch ---------------------------------------
extern "C" void kernel_launch(void* const* d_in, const int* in_sizes, int n_in,
                              void* d_out, int out_size)
{
    const float* x      = (const float*)d_in[0];
    const float* v1     = (const float*)d_in[1];
    const float* g1     = (const float*)d_in[2];
    const float* bias1  = (const float*)d_in[3];
    const float* v2     = (const float*)d_in[4];
    const float* g2     = (const float*)d_in[5];
    const float* bias2  = (const float*)d_in[6];
    const float* alpha1 = (const float*)d_in[7];
    const float* beta1  = (const float*)d_in[8];
    const float* alpha2 = (const float*)d_in[9];
    const float* beta2  = (const float*)d_in[10];
    float* out = (float*)d_out;

    __half *aA, *w1, *w2;
    float *c1, *a2c, *binv;
    cudaGetSymbolAddress((void**)&aA,   g_actT);
    cudaGetSymbolAddress((void**)&c1,   g_c1);
    cudaGetSymbolAddress((void**)&w1,   g_w1);
    cudaGetSymbolAddress((void**)&w2,   g_w2);
    cudaGetSymbolAddress((void**)&a2c,  g_a2c);
    cudaGetSymbolAddress((void**)&binv, g_binv);

    static bool attr_set = false;
    if (!attr_set) {
        cudaFuncSetAttribute(conv_mma_kernel,
                             cudaFuncAttributeMaxDynamicSharedMemorySize, SM_TOTAL);
        attr_set = true;
    }

    wnorm_kernel<<<CCH, 256>>>(v1, g1, alpha1, beta1, w1, a2c,       binv);
    wnorm_kernel<<<CCH, 256>>>(v2, g2, alpha2, beta2, w2, a2c + CCH, binv + CCH);

    dim3 agrid(TT / ATT, CCH / ATI, BSZ);

    snake_actT_kernel<<<agrid, 256>>>(x, a2c, binv, aA);
    conv_mma_kernel<<<GRID, CTN, SM_TOTAL>>>(aA, w1, bias1, nullptr, c1);
    snake_actT_kernel<<<agrid, 256>>>(c1, a2c + CCH, binv + CCH, aA);
    conv_mma_kernel<<<GRID, CTN, SM_TOTAL>>>(aA, w2, bias2, x, out);
}